// round 1
// baseline (speedup 1.0000x reference)
#include <cuda_runtime.h>
#include <math.h>

#define N_NODES_MAX 50000
#define N_GRAPHS 512
#define HID 128

// ---------------- scratch (static device allocations) ----------------
__device__ float g_h[(size_t)N_NODES_MAX * HID];    // X @ W
__device__ float g_agg[(size_t)N_NODES_MAX * HID];  // scatter-add target
__device__ float g_act[(size_t)N_NODES_MAX * HID];  // relu(agg + self + b)
__device__ float g_deg[N_NODES_MAX];
__device__ float g_dinv[N_NODES_MAX];   // 1/sqrt(deg+1)
__device__ float g_invd[N_NODES_MAX];   // 1/(deg+1)
__device__ float g_sums[N_GRAPHS * HID];
__device__ float g_cnt[N_GRAPHS];
__device__ int   g_is64;                // 1 if index arrays are int64, 0 if int32

// ---------------- small helpers ----------------
__device__ __forceinline__ unsigned long long pk2(float a, float b) {
    unsigned long long r;
    asm("mov.b64 %0, {%1, %2};" : "=l"(r) : "f"(a), "f"(b));
    return r;
}
__device__ __forceinline__ float2 upk2(unsigned long long v) {
    float2 f;
    asm("mov.b64 {%0, %1}, %2;" : "=f"(f.x), "=f"(f.y) : "l"(v));
    return f;
}
// packed dual-FMA: d = a*b + d  (2 fp32 lanes per instruction)
__device__ __forceinline__ void ffma2(unsigned long long& d, unsigned long long a,
                                      unsigned long long b) {
    asm("fma.rn.f32x2 %0, %1, %2, %3;" : "=l"(d) : "l"(a), "l"(b), "l"(d));
}

__device__ __forceinline__ int load_idx(const void* p, long i, int is64) {
    if (is64) return (int)((const long long*)p)[i];
    return ((const int*)p)[i];
}

// vector reduction (no return) into global memory
__device__ __forceinline__ void red_add_v4(float* addr, float4 v) {
    size_t ga = __cvta_generic_to_global(addr);
    asm volatile("red.global.add.v4.f32 [%0], {%1, %2, %3, %4};"
                 :: "l"(ga), "f"(v.x), "f"(v.y), "f"(v.z), "f"(v.w) : "memory");
}

// ---------------- index dtype detection ----------------
// int64 data: values < 50000 => top 32 bits of every u64 word are 0.
// int32 data reinterpreted as u64: top word = a uniform random index, ~never 0
// sixteen times in a row.
__global__ void detect_k(const unsigned long long* __restrict__ e) {
    if (threadIdx.x == 0 && blockIdx.x == 0) {
        int f = 1;
        for (int i = 0; i < 16; i++)
            if (e[i] >> 32) f = 0;
        g_is64 = f;
    }
}

// ---------------- degree ----------------
__global__ void deg_k(const void* __restrict__ ei, int E) {
    int e = blockIdx.x * blockDim.x + threadIdx.x;
    if (e >= E) return;
    int is64 = g_is64;
    int d = load_idx(ei, (long)E + e, is64);
    atomicAdd(&g_deg[d], 1.0f);
}

__global__ void dinv_k(int n) {
    int i = blockIdx.x * blockDim.x + threadIdx.x;
    if (i >= n) return;
    float dg = g_deg[i] + 1.0f;
    float r = rsqrtf(dg);
    g_dinv[i] = r;
    g_invd[i] = 1.0f / dg;
}

// ---------------- dense transform: g_h = X @ W  (W: [KIN,128]) ----------------
// 256 threads, 64 rows x 128 cols per block; each thread: 8 rows x 4 cols,
// accumulators in packed f32x2.
template <int KIN>
__global__ void gemm_k(const float* __restrict__ X, const float* __restrict__ W, int n) {
    __shared__ float Ws[32 * 128];
    __shared__ float Xs[64 * 32];
    const int tid  = threadIdx.x;
    const int lane = tid & 31;
    const int warp = tid >> 5;
    const int rbase = blockIdx.x * 64;

    unsigned long long acc[8][2];
#pragma unroll
    for (int r = 0; r < 8; r++) { acc[r][0] = 0ull; acc[r][1] = 0ull; }

    const int KT = KIN / 32;
    for (int kt = 0; kt < KT; kt++) {
        // stage W tile: 32x128 floats = 1024 float4, contiguous
#pragma unroll
        for (int j = 0; j < 4; j++) {
            int f = tid + j * 256;
            ((float4*)Ws)[f] = ((const float4*)W)[kt * 1024 + f];
        }
        // stage X tile: 64 rows x 32 k = 512 float4
#pragma unroll
        for (int j = 0; j < 2; j++) {
            int f = tid + j * 256;
            int row = f >> 3;     // 8 float4 per row
            int kk4 = f & 7;
            int gr = rbase + row;
            float4 v = make_float4(0.f, 0.f, 0.f, 0.f);
            if (gr < n)
                v = *(const float4*)(X + (long)gr * KIN + kt * 32 + kk4 * 4);
            ((float4*)Xs)[f] = v;
        }
        __syncthreads();
#pragma unroll
        for (int k = 0; k < 32; k++) {
            float4 wv = ((const float4*)Ws)[k * 32 + lane];
            unsigned long long w01 = pk2(wv.x, wv.y);
            unsigned long long w23 = pk2(wv.z, wv.w);
#pragma unroll
            for (int r = 0; r < 8; r++) {
                float xr = Xs[(warp * 8 + r) * 32 + k];
                unsigned long long xx = pk2(xr, xr);
                ffma2(acc[r][0], xx, w01);
                ffma2(acc[r][1], xx, w23);
            }
        }
        __syncthreads();
    }
#pragma unroll
    for (int r = 0; r < 8; r++) {
        int row = rbase + warp * 8 + r;
        if (row < n) {
            float2 a = upk2(acc[r][0]);
            float2 b = upk2(acc[r][1]);
            *(float4*)(g_h + (long)row * HID + lane * 4) =
                make_float4(a.x, a.y, b.x, b.y);
        }
    }
}

// ---------------- edge scatter: g_agg[dst] += g_h[src] * norm ----------------
// one warp per edge; lane handles 4 consecutive channels
__global__ void scatter_k(const void* __restrict__ ei, int E) {
    int gw = (blockIdx.x * blockDim.x + threadIdx.x) >> 5;
    if (gw >= E) return;
    int lane = threadIdx.x & 31;
    int is64 = g_is64;
    int s = load_idx(ei, gw, is64);
    int d = load_idx(ei, (long)E + gw, is64);
    float norm = g_dinv[s] * g_dinv[d];
    float4 v = *(const float4*)(g_h + (long)s * HID + lane * 4);
    v.x *= norm; v.y *= norm; v.z *= norm; v.w *= norm;
    red_add_v4(g_agg + (long)d * HID + lane * 4, v);
}

// ---------------- epilogue: g_act = relu(g_agg + g_h * invd + b) ----------------
__global__ void finalize_k(const float* __restrict__ b, int total) {
    int gid = blockIdx.x * blockDim.x + threadIdx.x;
    if (gid >= total) return;
    int node = gid >> 5;
    int c = gid & 31;
    long off = (long)node * HID + c * 4;
    float4 a = *(const float4*)(g_agg + off);
    float4 h = *(const float4*)(g_h + off);
    float id = g_invd[node];
    float4 bb = *(const float4*)(b + c * 4);
    float4 r;
    r.x = fmaxf(fmaf(h.x, id, a.x) + bb.x, 0.f);
    r.y = fmaxf(fmaf(h.y, id, a.y) + bb.y, 0.f);
    r.z = fmaxf(fmaf(h.z, id, a.z) + bb.z, 0.f);
    r.w = fmaxf(fmaf(h.w, id, a.w) + bb.w, 0.f);
    *(float4*)(g_act + off) = r;
}

// ---------------- pool: per-graph sums + counts ----------------
__global__ void pool_k(const void* __restrict__ batch, int n) {
    int node = (blockIdx.x * blockDim.x + threadIdx.x) >> 5;
    if (node >= n) return;
    int lane = threadIdx.x & 31;
    int is64 = g_is64;
    int g = load_idx(batch, node, is64);
    float4 v = *(const float4*)(g_act + (long)node * HID + lane * 4);
    red_add_v4(g_sums + (long)g * HID + lane * 4, v);
    if (lane == 0) atomicAdd(&g_cnt[g], 1.0f);
}

// ---------------- mean + final linear ----------------
__global__ void final_k(const float* __restrict__ Wlin, const float* __restrict__ blin,
                        float* __restrict__ out) {
    int g = blockIdx.x;
    int t = threadIdx.x;  // 128 threads
    float c = fmaxf(g_cnt[g], 1.0f);
    float s = g_sums[g * HID + t] / c;
    float p0 = s * Wlin[2 * t];
    float p1 = s * Wlin[2 * t + 1];
#pragma unroll
    for (int off = 16; off; off >>= 1) {
        p0 += __shfl_down_sync(0xffffffffu, p0, off);
        p1 += __shfl_down_sync(0xffffffffu, p1, off);
    }
    __shared__ float s0[4], s1[4];
    int w = t >> 5;
    if ((t & 31) == 0) { s0[w] = p0; s1[w] = p1; }
    __syncthreads();
    if (t == 0) {
        out[g * 2 + 0] = s0[0] + s0[1] + s0[2] + s0[3] + blin[0];
        out[g * 2 + 1] = s1[0] + s1[1] + s1[2] + s1[3] + blin[1];
    }
}

// ---------------- launcher ----------------
extern "C" void kernel_launch(void* const* d_in, const int* in_sizes, int n_in,
                              void* d_out, int out_size) {
    (void)out_size;
    const float* x     = (const float*)d_in[0];
    const void*  ei    = d_in[1];
    const void*  batch = d_in[2];
    // num_graphs may or may not be materialized as an input tensor
    int base = (n_in >= 10) ? 4 : 3;
    const float* W1   = (const float*)d_in[base + 0];
    const float* b1   = (const float*)d_in[base + 1];
    const float* W2   = (const float*)d_in[base + 2];
    const float* b2   = (const float*)d_in[base + 3];
    const float* Wlin = (const float*)d_in[base + 4];
    const float* blin = (const float*)d_in[base + 5];

    const int N = in_sizes[0] / 96;   // 50000
    const int E = in_sizes[1] / 2;    // 800000 (element count same for i32/i64)
    float* out = (float*)d_out;

    void *p_deg, *p_agg, *p_sums, *p_cnt, *p_act;
    cudaGetSymbolAddress(&p_deg, g_deg);
    cudaGetSymbolAddress(&p_agg, g_agg);
    cudaGetSymbolAddress(&p_sums, g_sums);
    cudaGetSymbolAddress(&p_cnt, g_cnt);
    cudaGetSymbolAddress(&p_act, g_act);

    cudaMemsetAsync(p_deg, 0, (size_t)N * sizeof(float), 0);
    cudaMemsetAsync(p_agg, 0, (size_t)N * HID * sizeof(float), 0);
    cudaMemsetAsync(p_sums, 0, (size_t)N_GRAPHS * HID * sizeof(float), 0);
    cudaMemsetAsync(p_cnt, 0, (size_t)N_GRAPHS * sizeof(float), 0);

    detect_k<<<1, 32>>>((const unsigned long long*)ei);
    deg_k<<<(E + 255) / 256, 256>>>(ei, E);
    dinv_k<<<(N + 255) / 256, 256>>>(N);

    // ---- layer 1 ----
    gemm_k<96><<<(N + 63) / 64, 256>>>(x, W1, N);
    scatter_k<<<(E + 7) / 8, 256>>>(ei, E);
    finalize_k<<<(N * 32 + 255) / 256, 256>>>(b1, N * 32);

    // ---- layer 2 ----
    cudaMemsetAsync(p_agg, 0, (size_t)N * HID * sizeof(float), 0);
    gemm_k<128><<<(N + 63) / 64, 256>>>((const float*)p_act, W2, N);
    scatter_k<<<(E + 7) / 8, 256>>>(ei, E);
    finalize_k<<<(N * 32 + 255) / 256, 256>>>(b2, N * 32);

    // ---- pool + head ----
    pool_k<<<(N + 7) / 8, 256>>>(batch, N);
    final_k<<<N_GRAPHS, HID>>>(Wlin, blin, out);
}

// round 2
// speedup vs baseline: 1.4201x; 1.4201x over previous
#include <cuda_runtime.h>
#include <math.h>

#define N_NODES_MAX 50000
#define E_MAX 800000
#define N_GRAPHS 512
#define HID 128

typedef unsigned long long ull;

// ---------------- scratch (static device allocations) ----------------
__device__ float g_a[(size_t)N_NODES_MAX * HID];    // gather output (<=128 cols)
__device__ float g_h[(size_t)N_NODES_MAX * HID];    // gemm output (h1, then h2)
__device__ int   g_degi[N_NODES_MAX];
__device__ int   g_off[N_NODES_MAX + 1];
__device__ int   g_cur[N_NODES_MAX];
__device__ float g_dinv[N_NODES_MAX];   // 1/sqrt(deg+1)
__device__ float g_invd[N_NODES_MAX];   // 1/(deg+1)
__device__ ull   g_csr[E_MAX];          // per-edge {norm(hi32), src(lo32)} grouped by dst
__device__ float g_sums[N_GRAPHS * HID];
__device__ float g_cnt[N_GRAPHS];
__device__ int   g_is64;                // 1 if index arrays are int64

// ---------------- packed f32x2 helpers ----------------
__device__ __forceinline__ ull pk2(float a, float b) {
    ull r;
    asm("mov.b64 %0, {%1, %2};" : "=l"(r) : "f"(a), "f"(b));
    return r;
}
__device__ __forceinline__ float2 upk2(ull v) {
    float2 f;
    asm("mov.b64 {%0, %1}, %2;" : "=f"(f.x), "=f"(f.y) : "l"(v));
    return f;
}
__device__ __forceinline__ void ffma2(ull& d, ull a, ull b) {
    asm("fma.rn.f32x2 %0, %1, %2, %3;" : "=l"(d) : "l"(a), "l"(b), "l"(d));
}

__device__ __forceinline__ int load_idx(const void* p, long i, int is64) {
    if (is64) return (int)((const long long*)p)[i];
    return ((const int*)p)[i];
}

__device__ __forceinline__ void red_add_v4(float* addr, float4 v) {
    size_t ga = __cvta_generic_to_global(addr);
    asm volatile("red.global.add.v4.f32 [%0], {%1, %2, %3, %4};"
                 :: "l"(ga), "f"(v.x), "f"(v.y), "f"(v.z), "f"(v.w) : "memory");
}

// ---------------- index dtype detection ----------------
__global__ void detect_k(const ull* __restrict__ e) {
    if (threadIdx.x == 0 && blockIdx.x == 0) {
        int f = 1;
        for (int i = 0; i < 16; i++)
            if (e[i] >> 32) f = 0;
        g_is64 = f;
    }
}

// ---------------- degree histogram ----------------
__global__ void deg_k(const void* __restrict__ ei, int E) {
    int e = blockIdx.x * blockDim.x + threadIdx.x;
    if (e >= E) return;
    int d = load_idx(ei, (long)E + e, g_is64);
    atomicAdd(&g_degi[d], 1);
}

// ---------------- exclusive scan over g_degi -> g_off (single block) ---------
__global__ void scan_k(int n) {
    __shared__ int wsum[32];
    __shared__ int carry;
    const int tid = threadIdx.x, lane = tid & 31, w = tid >> 5;
    if (tid == 0) carry = 0;
    __syncthreads();
    for (int base = 0; base < n; base += 1024) {
        int i = base + tid;
        int v = (i < n) ? g_degi[i] : 0;
        int x = v;
#pragma unroll
        for (int o = 1; o < 32; o <<= 1) {
            int y = __shfl_up_sync(~0u, x, o);
            if (lane >= o) x += y;
        }
        if (lane == 31) wsum[w] = x;
        __syncthreads();
        if (w == 0) {
            int s = wsum[lane];
#pragma unroll
            for (int o = 1; o < 32; o <<= 1) {
                int y = __shfl_up_sync(~0u, s, o);
                if (lane >= o) s += y;
            }
            wsum[lane] = s;
        }
        __syncthreads();
        int prefix = (w > 0) ? wsum[w - 1] : 0;
        if (i < n) g_off[i] = carry + prefix + x - v;
        int total = wsum[31];
        __syncthreads();
        if (tid == 0) carry += total;
        __syncthreads();
    }
    if (tid == 0) g_off[n] = carry;
}

// ---------------- norms + cursor init ----------------
__global__ void dinv_k(int n) {
    int i = blockIdx.x * blockDim.x + threadIdx.x;
    if (i >= n) return;
    float dg = (float)g_degi[i] + 1.0f;
    g_dinv[i] = rsqrtf(dg);
    g_invd[i] = 1.0f / dg;
    g_cur[i] = g_off[i];
}

// ---------------- CSR fill: per-edge record {norm, src} grouped by dst ------
__global__ void fill_k(const void* __restrict__ ei, int E) {
    int e = blockIdx.x * blockDim.x + threadIdx.x;
    if (e >= E) return;
    int is64 = g_is64;
    int s = load_idx(ei, e, is64);
    int d = load_idx(ei, (long)E + e, is64);
    float norm = g_dinv[s] * g_dinv[d];
    int pos = atomicAdd(&g_cur[d], 1);
    g_csr[pos] = ((ull)__float_as_uint(norm) << 32) | (unsigned)s;
}

// ---------------- gather-reduce: out[i] = sum_e norm*feat[src] + feat[i]/deg -
// one warp per dst node, no atomics
template <int CH>
__global__ void gather_k(const float* __restrict__ feat, float* __restrict__ out, int n) {
    int node = blockIdx.x * 8 + (threadIdx.x >> 5);
    if (node >= n) return;
    const int lane = threadIdx.x & 31;
    int p = g_off[node], end = g_off[node + 1];

    if (CH == 128) {
        const float4* f4 = (const float4*)feat;
        float4 acc = make_float4(0.f, 0.f, 0.f, 0.f);
        for (; p + 2 <= end; p += 2) {
            ull e0 = g_csr[p], e1 = g_csr[p + 1];
            int s0 = (int)(unsigned)e0; float n0 = __uint_as_float((unsigned)(e0 >> 32));
            int s1 = (int)(unsigned)e1; float n1 = __uint_as_float((unsigned)(e1 >> 32));
            float4 v0 = f4[(long)s0 * 32 + lane];
            float4 v1 = f4[(long)s1 * 32 + lane];
            acc.x = fmaf(v0.x, n0, fmaf(v1.x, n1, acc.x));
            acc.y = fmaf(v0.y, n0, fmaf(v1.y, n1, acc.y));
            acc.z = fmaf(v0.z, n0, fmaf(v1.z, n1, acc.z));
            acc.w = fmaf(v0.w, n0, fmaf(v1.w, n1, acc.w));
        }
        if (p < end) {
            ull e0 = g_csr[p];
            int s0 = (int)(unsigned)e0; float n0 = __uint_as_float((unsigned)(e0 >> 32));
            float4 v0 = f4[(long)s0 * 32 + lane];
            acc.x = fmaf(v0.x, n0, acc.x);
            acc.y = fmaf(v0.y, n0, acc.y);
            acc.z = fmaf(v0.z, n0, acc.z);
            acc.w = fmaf(v0.w, n0, acc.w);
        }
        float id = g_invd[node];
        float4 sv = f4[(long)node * 32 + lane];
        acc.x = fmaf(sv.x, id, acc.x);
        acc.y = fmaf(sv.y, id, acc.y);
        acc.z = fmaf(sv.z, id, acc.z);
        acc.w = fmaf(sv.w, id, acc.w);
        ((float4*)out)[(long)node * 32 + lane] = acc;
    } else {  // CH == 96: per-lane channels lane, lane+32, lane+64
        float a0 = 0.f, a1 = 0.f, a2 = 0.f;
        for (; p + 2 <= end; p += 2) {
            ull e0 = g_csr[p], e1 = g_csr[p + 1];
            int s0 = (int)(unsigned)e0; float n0 = __uint_as_float((unsigned)(e0 >> 32));
            int s1 = (int)(unsigned)e1; float n1 = __uint_as_float((unsigned)(e1 >> 32));
            const float* r0 = feat + (long)s0 * 96 + lane;
            const float* r1 = feat + (long)s1 * 96 + lane;
            float u0 = r0[0], u1 = r0[32], u2 = r0[64];
            float w0 = r1[0], w1 = r1[32], w2 = r1[64];
            a0 = fmaf(u0, n0, fmaf(w0, n1, a0));
            a1 = fmaf(u1, n0, fmaf(w1, n1, a1));
            a2 = fmaf(u2, n0, fmaf(w2, n1, a2));
        }
        if (p < end) {
            ull e0 = g_csr[p];
            int s0 = (int)(unsigned)e0; float n0 = __uint_as_float((unsigned)(e0 >> 32));
            const float* r0 = feat + (long)s0 * 96 + lane;
            a0 = fmaf(r0[0], n0, a0);
            a1 = fmaf(r0[32], n0, a1);
            a2 = fmaf(r0[64], n0, a2);
        }
        float id = g_invd[node];
        const float* sv = feat + (long)node * 96 + lane;
        a0 = fmaf(sv[0], id, a0);
        a1 = fmaf(sv[32], id, a1);
        a2 = fmaf(sv[64], id, a2);
        float* o = out + (long)node * 96 + lane;
        o[0] = a0; o[32] = a1; o[64] = a2;
    }
}

// ------- dense transform + epilogue: out = relu(X @ W + b), W: [KIN,128] ----
// 256 threads; 64 rows x 128 cols per block; pre-packed f32x2 operands in smem
template <int KIN>
__global__ void gemm_k(const float* __restrict__ X, const float* __restrict__ W,
                       const float* __restrict__ bias, float* __restrict__ out, int n) {
    __shared__ ulonglong2 Ws2[32 * 32];  // [k][col4] -> (w01, w23)   16KB
    __shared__ ull Xs2[64 * 32];         // [row][k]  -> (x, x)       16KB
    const int tid  = threadIdx.x;
    const int lane = tid & 31;
    const int warp = tid >> 5;
    const int rbase = blockIdx.x * 64;

    ull acc[8][2];
#pragma unroll
    for (int r = 0; r < 8; r++) { acc[r][0] = 0ull; acc[r][1] = 0ull; }

    const int KT = KIN / 32;
    for (int kt = 0; kt < KT; kt++) {
        // stage W tile pre-packed: 32x128 floats = 1024 float4
#pragma unroll
        for (int j = 0; j < 4; j++) {
            int f = tid + j * 256;
            float4 w = ((const float4*)W)[kt * 1024 + f];
            Ws2[f] = make_ulonglong2(pk2(w.x, w.y), pk2(w.z, w.w));
        }
        // stage X tile, duplicated into both f32x2 lanes: 64 rows x 32 k
#pragma unroll
        for (int j = 0; j < 2; j++) {
            int f = tid + j * 256;      // 512 float4
            int row = f >> 3;
            int kq = f & 7;
            int gr = rbase + row;
            float4 v = make_float4(0.f, 0.f, 0.f, 0.f);
            if (gr < n)
                v = *(const float4*)(X + (long)gr * KIN + kt * 32 + kq * 4);
            int bb = row * 32 + kq * 4;
            Xs2[bb + 0] = pk2(v.x, v.x);
            Xs2[bb + 1] = pk2(v.y, v.y);
            Xs2[bb + 2] = pk2(v.z, v.z);
            Xs2[bb + 3] = pk2(v.w, v.w);
        }
        __syncthreads();
#pragma unroll
        for (int k = 0; k < 32; k++) {
            ulonglong2 w = Ws2[k * 32 + lane];
#pragma unroll
            for (int r = 0; r < 8; r++) {
                ull xx = Xs2[(warp * 8 + r) * 32 + k];
                ffma2(acc[r][0], xx, w.x);
                ffma2(acc[r][1], xx, w.y);
            }
        }
        __syncthreads();
    }
    float4 bb = ((const float4*)bias)[lane];
#pragma unroll
    for (int r = 0; r < 8; r++) {
        int row = rbase + warp * 8 + r;
        if (row < n) {
            float2 a = upk2(acc[r][0]);
            float2 b = upk2(acc[r][1]);
            float4 o;
            o.x = fmaxf(a.x + bb.x, 0.f);
            o.y = fmaxf(a.y + bb.y, 0.f);
            o.z = fmaxf(b.x + bb.z, 0.f);
            o.w = fmaxf(b.y + bb.w, 0.f);
            *(float4*)(out + (long)row * HID + lane * 4) = o;
        }
    }
}

// ---------------- pool: per-graph sums + counts ----------------
__global__ void pool_k(const void* __restrict__ batch, int n) {
    int node = (blockIdx.x * blockDim.x + threadIdx.x) >> 5;
    if (node >= n) return;
    int lane = threadIdx.x & 31;
    int g = load_idx(batch, node, g_is64);
    float4 v = *(const float4*)(g_h + (long)node * HID + lane * 4);
    red_add_v4(g_sums + (long)g * HID + lane * 4, v);
    if (lane == 0) atomicAdd(&g_cnt[g], 1.0f);
}

// ---------------- mean + final linear ----------------
__global__ void final_k(const float* __restrict__ Wlin, const float* __restrict__ blin,
                        float* __restrict__ out) {
    int g = blockIdx.x;
    int t = threadIdx.x;  // 128
    float c = fmaxf(g_cnt[g], 1.0f);
    float s = g_sums[g * HID + t] / c;
    float p0 = s * Wlin[2 * t];
    float p1 = s * Wlin[2 * t + 1];
#pragma unroll
    for (int off = 16; off; off >>= 1) {
        p0 += __shfl_down_sync(0xffffffffu, p0, off);
        p1 += __shfl_down_sync(0xffffffffu, p1, off);
    }
    __shared__ float s0[4], s1[4];
    int w = t >> 5;
    if ((t & 31) == 0) { s0[w] = p0; s1[w] = p1; }
    __syncthreads();
    if (t == 0) {
        out[g * 2 + 0] = s0[0] + s0[1] + s0[2] + s0[3] + blin[0];
        out[g * 2 + 1] = s1[0] + s1[1] + s1[2] + s1[3] + blin[1];
    }
}

// ---------------- launcher ----------------
extern "C" void kernel_launch(void* const* d_in, const int* in_sizes, int n_in,
                              void* d_out, int out_size) {
    (void)out_size;
    const float* x     = (const float*)d_in[0];
    const void*  ei    = d_in[1];
    const void*  batch = d_in[2];
    int base = (n_in >= 10) ? 4 : 3;
    const float* W1   = (const float*)d_in[base + 0];
    const float* b1   = (const float*)d_in[base + 1];
    const float* W2   = (const float*)d_in[base + 2];
    const float* b2   = (const float*)d_in[base + 3];
    const float* Wlin = (const float*)d_in[base + 4];
    const float* blin = (const float*)d_in[base + 5];

    const int N = in_sizes[0] / 96;
    const int E = in_sizes[1] / 2;
    float* out = (float*)d_out;

    void *p_degi, *p_sums, *p_cnt, *p_a, *p_h;
    cudaGetSymbolAddress(&p_degi, g_degi);
    cudaGetSymbolAddress(&p_sums, g_sums);
    cudaGetSymbolAddress(&p_cnt, g_cnt);
    cudaGetSymbolAddress(&p_a, g_a);
    cudaGetSymbolAddress(&p_h, g_h);

    cudaMemsetAsync(p_degi, 0, (size_t)N * sizeof(int), 0);
    cudaMemsetAsync(p_sums, 0, (size_t)N_GRAPHS * HID * sizeof(float), 0);
    cudaMemsetAsync(p_cnt, 0, (size_t)N_GRAPHS * sizeof(float), 0);

    detect_k<<<1, 32>>>((const ull*)ei);
    deg_k<<<(E + 255) / 256, 256>>>(ei, E);
    scan_k<<<1, 1024>>>(N);
    dinv_k<<<(N + 255) / 256, 256>>>(N);
    fill_k<<<(E + 255) / 256, 256>>>(ei, E);

    // layer 1: aggregate x (96 cols) first, then transform (+bias+relu fused)
    gather_k<96><<<(N + 7) / 8, 256>>>(x, (float*)p_a, N);
    gemm_k<96><<<(N + 63) / 64, 256>>>((const float*)p_a, W1, b1, (float*)p_h, N);

    // layer 2
    gather_k<128><<<(N + 7) / 8, 256>>>((const float*)p_h, (float*)p_a, N);
    gemm_k<128><<<(N + 63) / 64, 256>>>((const float*)p_a, W2, b2, (float*)p_h, N);

    // pool + head
    pool_k<<<(N + 7) / 8, 256>>>(batch, N);
    final_k<<<N_GRAPHS, HID>>>(Wlin, blin, out);
}